// round 13
// baseline (speedup 1.0000x reference)
#include <cuda_runtime.h>
#include <cfloat>

// Problem constants (from reference)
#define PB 7      // pooled bins per dim
#define HH 50
#define WW 50
#define CC 512
#define BB 2
#define RR 64
#define C4 (CC / 4)     // 128 float4 per pixel
#define NBINS (BB * RR * PB * PB)   // 6272
#define NCTA  2368                  // 148 SMs x 16 CTAs: exact full-residency wave

// Full-occupancy single-wave kernel. Grid 2368 = 148*16 so every SM holds
// its maximum 16 CTAs (64 warps) from the start; each CTA strides through
// bins {bid, bid+2368, ...} (2 or 3 bins). Inner body identical to the
// 10.21us best: integer bin bounds, roi-for-next-iteration prefetched ahead
// of the current gather, CTA-uniform 16-case exact-load dispatch.
//
// Integer bin bounds ys = py*h/7 == reference fp32 trunc(py*(h/7.0f)) for
// h in [7,25]: exact when 7|h, else py*h/7 is >=1/7 from any integer, far
// beyond fp32 rounding error. (Validated rel_err=0.0 in R10-R12.)
//
// Facts proved from input ranges: extent in [7,26) => sy,sx in [1,4];
// window always fully in-bounds (max index y0+h-1 <= 48 < 50).

__device__ __forceinline__ void vmax(float4& m, float4 v) {
    m.x = fmaxf(m.x, v.x);
    m.y = fmaxf(m.y, v.y);
    m.z = fmaxf(m.z, v.z);
    m.w = fmaxf(m.w, v.w);
}

template<int SY, int SX>
__device__ __forceinline__ float4 binmax(const float4* __restrict__ p) {
    float4 v[SY * SX];
    #pragma unroll
    for (int dy = 0; dy < SY; ++dy)
        #pragma unroll
        for (int dx = 0; dx < SX; ++dx)
            v[dy * SX + dx] = __ldg(p + (dy * WW + dx) * C4);

    float4 m = v[0];
    #pragma unroll
    for (int k = 1; k < SY * SX; ++k)
        vmax(m, v[k]);
    return m;
}

__global__ __launch_bounds__(C4) void roipool_kernel(
    const float4* __restrict__ fm,    // (B,H,W,C) as float4
    const int*    __restrict__ rois,  // (B,R,4) int32: y0,x0,h,w
    float4*       __restrict__ out)   // (B,R,P,P,C) as float4
{
    int c4 = threadIdx.x;             // 0..127

    // Prefetch the first bin's roi.
    int bin = blockIdx.x;
    int4 roi = __ldg((const int4*)(rois + (bin / (PB * PB)) * 4));

    for (; bin < NBINS; bin += NCTA) {
        // Prefetch next iteration's roi before this bin's gather.
        int nbin = bin + NCTA;
        int4 roi_n;
        if (nbin < NBINS)
            roi_n = __ldg((const int4*)(rois + (nbin / (PB * PB)) * 4));

        // Decode bin -> (rid, py, px). Constant div/mod -> magic multiplies.
        int rid  = bin / (PB * PB);
        int obin = bin - rid * (PB * PB);
        int py   = obin / PB;
        int px   = obin - py * PB;

        int y0 = roi.x, x0 = roi.y, h = roi.z, w = roi.w;

        // Integer bin bounds (== reference fp32 result, see header).
        int ys = (py * h) / PB;
        int ye = (py == PB - 1) ? h : ((py + 1) * h) / PB;
        int sy = max(ye - ys, 1);
        int xs = (px * w) / PB;
        int xe = (px == PB - 1) ? w : ((px + 1) * w) / PB;
        int sx = max(xe - xs, 1);

        // b = rid >> 6; fm image stride = HH*WW pixels.
        const float4* p = fm
            + ((size_t)(((rid >> 6) * HH + (y0 + ys)) * WW + (x0 + xs))) * C4
            + c4;

        float4 m;
        int code = (sy - 1) * 4 + (sx - 1);   // uniform across CTA
        switch (code) {
            case  0: m = binmax<1,1>(p); break;
            case  1: m = binmax<1,2>(p); break;
            case  2: m = binmax<1,3>(p); break;
            case  3: m = binmax<1,4>(p); break;
            case  4: m = binmax<2,1>(p); break;
            case  5: m = binmax<2,2>(p); break;
            case  6: m = binmax<2,3>(p); break;
            case  7: m = binmax<2,4>(p); break;
            case  8: m = binmax<3,1>(p); break;
            case  9: m = binmax<3,2>(p); break;
            case 10: m = binmax<3,3>(p); break;
            case 11: m = binmax<3,4>(p); break;
            case 12: m = binmax<4,1>(p); break;
            case 13: m = binmax<4,2>(p); break;
            case 14: m = binmax<4,3>(p); break;
            default: m = binmax<4,4>(p); break;
        }

        out[(size_t)bin * C4 + c4] = m;

        roi = roi_n;
    }
}

extern "C" void kernel_launch(void* const* d_in, const int* in_sizes, int n_in,
                              void* d_out, int out_size) {
    const float4* fm   = (const float4*)d_in[0];  // x_maps float32 (2,50,50,512)
    const int*    rois = (const int*)d_in[1];     // x_rois int32 (2,64,4)
    float4*       out  = (float4*)d_out;          // (2,64,7,7,512) float32

    roipool_kernel<<<NCTA, C4>>>(fm, rois, out);
}